// round 15
// baseline (speedup 1.0000x reference)
#include <cuda_runtime.h>

// FFTLayer: out = Re(FFT_512(x * win)) for 65536 rows of 512 fp32.
// Pack 2 real rows into one complex FFT (z = a + i*b); 512 = 8*8*8 radix-8,
// 64 threads per CTA = one FFT, 8 complex values in registers.
// float2-interleaved smem (LDS.64/STS.64) + symmetric dual-write epilogue.
// R13 fix: final natural-order layout stride 66 -> 72 (9*r2 + r reaches 70,
// which collided across 66-stride blocks and corrupted bins).

#define NFFT     512
#define THREADS  64
#define EX_SIZE  576   // exchanges: max 72*7+9*7+7 = 574 ; final layout same bound

__device__ __forceinline__ float2 cadd(float2 a, float2 b) { return make_float2(a.x + b.x, a.y + b.y); }
__device__ __forceinline__ float2 csub(float2 a, float2 b) { return make_float2(a.x - b.x, a.y - b.y); }
__device__ __forceinline__ float2 cmul(float2 a, float2 b) {
    return make_float2(a.x * b.x - a.y * b.y, a.x * b.y + a.y * b.x);
}
__device__ __forceinline__ float2 mnegi(float2 a) { return make_float2(a.y, -a.x); }

// In-place 8-point DIF FFT: v[r] <- sum_i v_in[i] * W8^{r*i},  W8 = e^{-2*pi*i/8}
__device__ __forceinline__ void fft8(float2 v[8]) {
    const float C = 0.70710678118654752440f;
    float2 a0 = cadd(v[0], v[4]), a4 = csub(v[0], v[4]);
    float2 a1 = cadd(v[1], v[5]), a5 = csub(v[1], v[5]);
    float2 a2 = cadd(v[2], v[6]), a6 = csub(v[2], v[6]);
    float2 a3 = cadd(v[3], v[7]), a7 = csub(v[3], v[7]);
    a5 = make_float2(C * (a5.x + a5.y), C * (a5.y - a5.x));
    a6 = mnegi(a6);
    a7 = make_float2(C * (a7.y - a7.x), -C * (a7.x + a7.y));
    float2 b0 = cadd(a0, a2), b2 = csub(a0, a2);
    float2 b1 = cadd(a1, a3), b3 = mnegi(csub(a1, a3));
    float2 b4 = cadd(a4, a6), b6 = csub(a4, a6);
    float2 b5 = cadd(a5, a7), b7 = mnegi(csub(a5, a7));
    v[0] = cadd(b0, b1); v[4] = csub(b0, b1);
    v[2] = cadd(b2, b3); v[6] = csub(b2, b3);
    v[1] = cadd(b4, b5); v[5] = csub(b4, b5);
    v[3] = cadd(b6, b7); v[7] = csub(b6, b7);
}

__device__ __forceinline__ void twiddle7(float2 v[8], float2 w1) {
    float2 wp = w1;
#pragma unroll
    for (int r = 1; r < 8; r++) {
        v[r] = cmul(v[r], wp);
        if (r < 7) wp = cmul(wp, w1);
    }
}

// address of X[k] in the final padded natural-order layout (stride 72: injective,
// since max intra-block offset 9*7 + 7 = 70 < 72)
__device__ __forceinline__ int faddr(int k) {
    return 72 * (k >> 6) + 9 * ((k >> 3) & 7) + (k & 7);
}

__global__ void __launch_bounds__(THREADS, 32)
fft512_real_kernel(const float* __restrict__ x,
                   const float* __restrict__ win,
                   float* __restrict__ out) {
    __shared__ float2 z[EX_SIZE];

    const int u    = threadIdx.x;     // 0..63
    const int pair = blockIdx.x;

    const float* xa = x + (size_t)pair * 2 * NFFT;
    const float* xb = xa + NFFT;
    float* oa = out + (size_t)pair * 2 * NFFT;
    float* ob = oa + NFFT;

    float2 v[8];

    // ---- Pass 1: load + window (0.5x folded in for the unpack), FFT8 over
    // elements u + 64*i, twiddle W512^{u*r}
#pragma unroll
    for (int i = 0; i < 8; i++) {
        const int idx = u + 64 * i;
        const float w = 0.5f * __ldg(&win[idx]);
        v[i].x = xa[idx] * w;
        v[i].y = xb[idx] * w;
    }
    fft8(v);
    {
        float s, c;
        sincospif(-(float)u * (1.0f / 256.0f), &s, &c);  // e^{-2 pi i u / 512}
        twiddle7(v, make_float2(c, s));
    }
    // exchange 1: y_r[q=u] at [72*r + u]
    // 64-bit banks: addr mod 16 consecutive over each 16-lane phase -> CF
#pragma unroll
    for (int r = 0; r < 8; r++) z[72 * r + u] = v[r];
    __syncthreads();

    // ---- Pass 2: thread = (r, q1). Gather [72r + q1 + 8q2]:
    // per 16-lane phase: mod16 = q1 + 8*((q2 + r) & 1)-style disjoint blocks -> CF.
    // FFT8 over q2, twiddle W64^{q1*r2}.
    const int r  = u >> 3;
    const int q1 = u & 7;
#pragma unroll
    for (int q2 = 0; q2 < 8; q2++) v[q2] = z[72 * r + q1 + 8 * q2];
    fft8(v);
    {
        float s, c;
        sincospif(-(float)q1 * (1.0f / 32.0f), &s, &c);  // e^{-2 pi i q1 / 64}
        twiddle7(v, make_float2(c, s));
    }
    __syncthreads();  // all exchange-1 reads done before overwrite
    // exchange 2: z_{r,r2}[q1] at [72*r + 9*r2 + q1]
#pragma unroll
    for (int r2 = 0; r2 < 8; r2++) z[72 * r + 9 * r2 + q1] = v[r2];
    __syncthreads();

    // ---- Pass 3: thread = (r, r2). Gather [72r + 9r2 + q1b]:
    // mod16 over phase lanes: 8r + 9r2 injective -> CF. FFT8, no twiddle.
    const int r2 = u & 7;
#pragma unroll
    for (int q1b = 0; q1b < 8; q1b++) v[q1b] = z[72 * r + 9 * r2 + q1b];
    fft8(v);
    __syncthreads();  // exchange-2 reads done before final-store reuse

    // final store, padded natural order: X[k = 64*k2 + 8*r2 + r] at
    // [72*k2 + 9*r2 + r]  (injective; one benign 2-way per phase in 64-bit mode)
#pragma unroll
    for (int k2 = 0; k2 < 8; k2++) z[72 * k2 + 9 * r2 + r] = v[k2];
    __syncthreads();

    // ---- Epilogue: symmetric unpack, each mirror pair computed once.
    // S_a(k) = Re Z[k] + Re Z[512-k],  S_b(k) = Im Z[k] + Im Z[512-k]
    // (0.5 folded into window). Real-input symmetry: out[k] == out[512-k].
#pragma unroll
    for (int jj = 0; jj < 4; jj++) {
        const int k  = u + 64 * jj;              // 0..255
        const int kk = (NFFT - k) & (NFFT - 1);  // mirror (257..511, or 0 at k=0)
        const float2 zk  = z[faddr(k)];
        const float2 zkk = z[faddr(kk)];
        const float sa = zk.x + zkk.x;
        const float sb = zk.y + zkk.y;
        oa[k]  = sa;  ob[k]  = sb;
        oa[kk] = sa;  ob[kk] = sb;   // k=0: duplicate write of same value, benign
    }
    if (u == 0) {  // k = 256 is its own mirror, not covered above
        const float2 zc = z[faddr(256)];
        oa[256] = zc.x + zc.x;
        ob[256] = zc.y + zc.y;
    }
}

extern "C" void kernel_launch(void* const* d_in, const int* in_sizes, int n_in,
                              void* d_out, int out_size) {
    const float* x   = (const float*)d_in[0];   // (256, 256, 512) fp32
    const float* win = (const float*)d_in[1];   // (512,) fp32
    float* out = (float*)d_out;                 // (256, 256, 512, 1) fp32

    const int n_rows  = in_sizes[0] / NFFT;     // 65536
    const int n_pairs = n_rows / 2;             // 32768

    fft512_real_kernel<<<n_pairs, THREADS>>>(x, win, out);
}